// round 15
// baseline (speedup 1.0000x reference)
#include <cuda_runtime.h>
#include <cstdint>

// Per-row stream compaction:
//   x3: [B*C, L] f32, L=16384. Drop entries exactly equal to 10.1f, keep
//   order, emit first KEEP=12288 survivors per row. Setup guarantees exactly
//   L-KEEP fillers per row, so output is fully written.
//
// R8: R7 showed cutting L1 wavefronts (67%->45%) did NOT move wall time ->
// limiter is phase serialization (4 barriers + smem staging round trip with
// only 2 CTAs/SM). Since R7's transposed ownership makes each warp's output
// a dense contiguous span that tiles the row exactly, scatter DIRECTLY to
// global: drop the 48 KB staging buffer, the drain phase, and 2 of 4
// barriers. Adjacent warps' partial sectors merge in L2 (dense tiling), so
// DRAM write traffic is unchanged.

#define FILLER 10.1f

constexpr int L_DIM   = 16384;
constexpr int KEEP    = 12288;
constexpr int THREADS = 1024;               // 32 warps
constexpr int CHUNK   = 512;                // elements per warp
constexpr int ROUNDS  = 4;                  // float4 rounds per thread

__global__ __launch_bounds__(THREADS, 2)
void compact_rows_kernel(const float* __restrict__ x3,
                         float* __restrict__ out,
                         int n_rows)
{
    __shared__ int warp_sums[32];

    const int row = blockIdx.x;
    if (row >= n_rows) return;

    const float* __restrict__ in = x3 + (size_t)row * L_DIM;
    float* __restrict__ o        = out + (size_t)row * KEEP;

    const int tid  = threadIdx.x;
    const int lane = tid & 31;
    const int wid  = tid >> 5;

    // Warp-contiguous chunk; thread t owns float4 at chunk + 128*i + 4*t.
    const float4* __restrict__ in4 =
        reinterpret_cast<const float4*>(in + wid * CHUNK);

    float4 q[ROUNDS];
#pragma unroll
    for (int i = 0; i < ROUNDS; ++i)
        q[i] = in4[i * 32 + lane];

    // Per-round survivor counts, byte-packed (each byte <= 4; scan sums <= 128).
    unsigned packed = 0;
    int      c[ROUNDS];
#pragma unroll
    for (int i = 0; i < ROUNDS; ++i) {
        int ci = (q[i].x != FILLER) + (q[i].y != FILLER) +
                 (q[i].z != FILLER) + (q[i].w != FILLER);
        c[i] = ci;
        packed |= (unsigned)ci << (8 * i);
    }

    // One SIMD warp scan covers all 4 rounds' lane prefixes.
    unsigned incp = packed;
#pragma unroll
    for (int d = 1; d < 32; d <<= 1) {
        unsigned y = __shfl_up_sync(0xFFFFFFFFu, incp, d);
        if (lane >= d) incp += y;
    }
    const unsigned tot = __shfl_sync(0xFFFFFFFFu, incp, 31); // warp totals/round

    const int t0 = tot & 0xFF, t1 = (tot >> 8) & 0xFF,
              t2 = (tot >> 16) & 0xFF, t3 = (tot >> 24) & 0xFF;
    const int warp_total = t0 + t1 + t2 + t3;

    // Block scan of warp totals (32 warps) — static smem, 2 barriers total.
    if (lane == 0) warp_sums[wid] = warp_total;
    __syncthreads();
    if (wid == 0) {
        int s = warp_sums[lane];
#pragma unroll
        for (int d = 1; d < 32; d <<= 1) {
            int y = __shfl_up_sync(0xFFFFFFFFu, s, d);
            if (lane >= d) s += y;
        }
        warp_sums[lane] = s;   // inclusive over warps <= lane
    }
    __syncthreads();
    const int warp_base = (wid > 0 ? warp_sums[wid - 1] : 0);

    // Round bases within the warp's dense output run.
    int B[ROUNDS];
    B[0] = 0; B[1] = t0; B[2] = t0 + t1; B[3] = t0 + t1 + t2;

    // Dense ordered scatter DIRECTLY to global: round i, lane t writes at
    // o[warp_base + B[i] + (exclusive lane prefix of round i) + quad prefix].
    // Warp spans tile the row densely, so L2 write-combines full sectors.
#pragma unroll
    for (int i = 0; i < ROUNDS; ++i) {
        int excl = (int)((incp >> (8 * i)) & 0xFF) - c[i];
        int off  = warp_base + B[i] + excl;
        const float4 t = q[i];
        if (t.x != FILLER) { if (off < KEEP) o[off] = t.x; ++off; }
        if (t.y != FILLER) { if (off < KEEP) o[off] = t.y; ++off; }
        if (t.z != FILLER) { if (off < KEEP) o[off] = t.z; ++off; }
        if (t.w != FILLER) { if (off < KEEP) o[off] = t.w; ++off; }
    }
}

extern "C" void kernel_launch(void* const* d_in, const int* in_sizes, int n_in,
                              void* d_out, int out_size)
{
    // metadata order: x1 [B,C,4096] f32, x2 [B,C,4096] f32,
    //                 x3 [B,C,16384] f32, keep_len (int scalar)
    const float* x3 = (const float*)d_in[2];
    float* out = (float*)d_out;

    const int n_rows = in_sizes[2] / L_DIM;   // B*C = 2048

    compact_rows_kernel<<<n_rows, THREADS>>>(x3, out, n_rows);
}

// round 17
// speedup vs baseline: 1.3082x; 1.3082x over previous
#include <cuda_runtime.h>
#include <cstdint>

// Per-row stream compaction:
//   x3: [B*C, L] f32, L=16384. Drop entries equal to 10.1f, keep order, emit
//   first KEEP=12288 survivors per row (setup guarantees exactly L-KEEP
//   fillers per row).
//
// R10: revert clusters (R9 crashed) and TMA (R6 regressed). Base = R7
// transposed-ownership smem staging, restructured to minimize barriers:
//   - every warp redundantly scans the 32 warp totals (kills the wid0-only
//     scan barrier),
//   - warp w scatters exclusively into its own span [warp_base_w, +total_w),
//     so the drain is warp-private: __syncwarp + scalar coalesced copy, no
//     post-scatter block barrier.
// Block barriers: 4 -> 2. warp_sums aliases stage[0..31]; S2 fences all
// reads of it before warp0's scatter can overwrite.

#define FILLER 10.1f

constexpr int L_DIM   = 16384;
constexpr int KEEP    = 12288;
constexpr int THREADS = 1024;               // 32 warps
constexpr int CHUNK   = 512;                // elements per warp
constexpr int ROUNDS  = 4;                  // float4 rounds per thread

__global__ __launch_bounds__(THREADS, 2)
void compact_rows_kernel(const float* __restrict__ x3,
                         float* __restrict__ out)
{
    extern __shared__ __align__(16) float stage[]; // 49152 B dynamic
    int* warp_sums = reinterpret_cast<int*>(stage); // transient alias

    const int row = blockIdx.x;

    const float* __restrict__ in = x3 + (size_t)row * L_DIM;
    float* __restrict__ o        = out + (size_t)row * KEEP;

    const int tid  = threadIdx.x;
    const int lane = tid & 31;
    const int wid  = tid >> 5;

    // Warp-contiguous chunk; thread t owns float4 at chunk + 128*i + 4*t
    // (input order == (wid, i, lane, k) lex order).
    const float4* __restrict__ in4 =
        reinterpret_cast<const float4*>(in + wid * CHUNK);

    float4 q[ROUNDS];
#pragma unroll
    for (int i = 0; i < ROUNDS; ++i)
        q[i] = in4[i * 32 + lane];

    // Per-round survivor counts, byte-packed (each byte <= 128 after scan).
    unsigned packed = 0;
    int      c[ROUNDS];
#pragma unroll
    for (int i = 0; i < ROUNDS; ++i) {
        int ci = (q[i].x != FILLER) + (q[i].y != FILLER) +
                 (q[i].z != FILLER) + (q[i].w != FILLER);
        c[i] = ci;
        packed |= (unsigned)ci << (8 * i);
    }

    // One SIMD warp scan covers all 4 rounds' lane prefixes.
    unsigned incp = packed;
#pragma unroll
    for (int d = 1; d < 32; d <<= 1) {
        unsigned y = __shfl_up_sync(0xFFFFFFFFu, incp, d);
        if (lane >= d) incp += y;
    }
    const unsigned tot = __shfl_sync(0xFFFFFFFFu, incp, 31); // warp totals/round

    const int t0 = tot & 0xFF, t1 = (tot >> 8) & 0xFF,
              t2 = (tot >> 16) & 0xFF, t3 = (tot >> 24) & 0xFF;
    const int warp_total = t0 + t1 + t2 + t3;

    if (lane == 0) warp_sums[wid] = warp_total;
    __syncthreads();                                  // S1

    // Every warp redundantly scans all 32 warp totals (5 shfl).
    int s = warp_sums[lane];
#pragma unroll
    for (int d = 1; d < 32; d <<= 1) {
        int y = __shfl_up_sync(0xFFFFFFFFu, s, d);
        if (lane >= d) s += y;
    }
    const int warp_base = (wid > 0)
        ? __shfl_sync(0xFFFFFFFFu, s, wid - 1) : 0;

    __syncthreads();                                  // S2: fences the
    // warp_sums reads above against warp0's scatter into stage[0..31].

    // Round bases within this warp's dense output run.
    int B[ROUNDS];
    B[0] = 0; B[1] = t0; B[2] = t0 + t1; B[3] = t0 + t1 + t2;

    // Dense ordered scatter into the warp's private span (near conflict-free).
#pragma unroll
    for (int i = 0; i < ROUNDS; ++i) {
        int excl = (int)((incp >> (8 * i)) & 0xFF) - c[i];
        int off  = warp_base + B[i] + excl;
        const float4 t = q[i];
        if (t.x != FILLER) { if (off < KEEP) stage[off] = t.x; ++off; }
        if (t.y != FILLER) { if (off < KEEP) stage[off] = t.y; ++off; }
        if (t.z != FILLER) { if (off < KEEP) stage[off] = t.z; ++off; }
        if (t.w != FILLER) { if (off < KEEP) stage[off] = t.w; ++off; }
    }
    __syncwarp();

    // Warp-private drain: only this warp wrote [warp_base, warp_base+total),
    // so no block barrier is needed. Coalesced 128B per iteration.
    const int end = min(warp_base + warp_total, KEEP);
    for (int j = warp_base + lane; j < end; j += 32)
        o[j] = stage[j];
}

extern "C" void kernel_launch(void* const* d_in, const int* in_sizes, int n_in,
                              void* d_out, int out_size)
{
    // metadata order: x1 [B,C,4096] f32, x2 [B,C,4096] f32,
    //                 x3 [B,C,16384] f32, keep_len (int scalar)
    const float* x3 = (const float*)d_in[2];
    float* out = (float*)d_out;

    const int n_rows = in_sizes[2] / L_DIM;            // B*C = 2048
    const int smem_bytes = KEEP * (int)sizeof(float);  // 49152 B dynamic

    compact_rows_kernel<<<n_rows, THREADS, smem_bytes>>>(x3, out);
}